// round 3
// baseline (speedup 1.0000x reference)
#include <cuda_runtime.h>

// RandomShiftsAug: out[n,c,j,i] = x[n, c, src_h(n,j), src_w(n,i)]
//   kx = shift[n,0], ky = shift[n,1]  (both in [0, 8])
//   th    = max(ky + j - 4, 0); src_h = th - 84*(th >= 84)
//   src_w = clamp(kx + i - 4, 0, 419)
//
// HBM-bound gather. Each thread: 4 consecutive output rows at one i4.
// Source span per output float4 = [base, base+3], base = 4*i4 + kx - 4.
// Misalignment o = kx & 3 is batch-uniform -> load 1-2 ALIGNED float4
// (LDG.128, fully coalesced) and combine with compile-time register picks
// in a 4-way branch on o. Edge vectors fall back to clamped scalar loads.

#define N_BATCH 128
#define CH      9
#define H       84
#define W       420
#define W4      (W / 4)               // 105
#define JG      (H / 4)               // 21
#define NWORK   (N_BATCH * CH * JG * W4)
#define THREADS 256
#define BLOCKS  ((NWORK + THREADS - 1) / THREADS)

__device__ __forceinline__ float4 ldg4(const float* p) {
    return __ldg((const float4*)p);
}

template <int O>
__device__ __forceinline__ void fast_path(const float* const rowp[4],
                                          int q,            // float index of aligned A
                                          float4* outp)
{
    float4 A[4], B[4];
#pragma unroll
    for (int jj = 0; jj < 4; jj++) {
        A[jj] = ldg4(rowp[jj] + q);
        if (O != 0) B[jj] = ldg4(rowp[jj] + q + 4);
    }
#pragma unroll
    for (int jj = 0; jj < 4; jj++) {
        float4 v;
        if (O == 0)      { v = A[jj]; }
        else if (O == 1) { v.x = A[jj].y; v.y = A[jj].z; v.z = A[jj].w; v.w = B[jj].x; }
        else if (O == 2) { v.x = A[jj].z; v.y = A[jj].w; v.z = B[jj].x; v.w = B[jj].y; }
        else             { v.x = A[jj].w; v.y = B[jj].x; v.z = B[jj].y; v.w = B[jj].z; }
        outp[jj * W4] = v;
    }
}

__global__ __launch_bounds__(THREADS)
void rand_shift_kernel(const float* __restrict__ x,
                       const int*   __restrict__ shift,
                       float4*      __restrict__ out)
{
    const int idx = blockIdx.x * THREADS + threadIdx.x;
    if (idx >= NWORK) return;

    // idx = ((nc*21 + jg)*105 + i4)
    const int i4 = idx % W4;
    const int r  = idx / W4;
    const int jg = r % JG;
    const int nc = r / JG;            // n*9 + c
    const int n  = nc / CH;

    const int kx = __ldg(&shift[2 * n]);
    const int ky = __ldg(&shift[2 * n + 1]);

    const int j0 = 4 * jg;

    // Row pointers for the 4 consecutive output rows (row map is column-free).
    const float* rowp[4];
#pragma unroll
    for (int jj = 0; jj < 4; jj++) {
        int th = ky + (j0 + jj) - 4;
        th = th < 0 ? 0 : th;
        const int src_h = (th >= H) ? (th - H) : th;
        rowp[jj] = x + (nc * H + src_h) * W;
    }

    float4* outp = out + (nc * H + j0) * W4 + i4;

    const int base = 4 * i4 + kx - 4;     // first source column
    const int o    = kx & 3;              // alignment offset (batch-uniform)
    const int a0   = base - o;            // aligned start (multiple of 4)

    bool fast;
    if (o == 0) fast = (base >= 0) && (base + 3 < W);
    else        fast = (a0 >= 0) && (a0 + 7 < W);

    if (fast) {
        if (o == 0)      fast_path<0>(rowp, a0, outp);
        else if (o == 1) fast_path<1>(rowp, a0, outp);
        else if (o == 2) fast_path<2>(rowp, a0, outp);
        else             fast_path<3>(rowp, a0, outp);
    } else {
        // Edge vectors: clamped scalar gather (rare: ~2% of threads).
        const int w0 = min(max(base,     0), W - 1);
        const int w1 = min(max(base + 1, 0), W - 1);
        const int w2 = min(max(base + 2, 0), W - 1);
        const int w3 = min(max(base + 3, 0), W - 1);
        float4 v[4];
#pragma unroll
        for (int jj = 0; jj < 4; jj++) {
            v[jj].x = __ldg(rowp[jj] + w0);
            v[jj].y = __ldg(rowp[jj] + w1);
            v[jj].z = __ldg(rowp[jj] + w2);
            v[jj].w = __ldg(rowp[jj] + w3);
        }
#pragma unroll
        for (int jj = 0; jj < 4; jj++) outp[jj * W4] = v[jj];
    }
}

extern "C" void kernel_launch(void* const* d_in, const int* in_sizes, int n_in,
                              void* d_out, int out_size)
{
    const float* x     = (const float*)d_in[0];
    const int*   shift = (const int*)d_in[1];
    float4*      out   = (float4*)d_out;

    rand_shift_kernel<<<BLOCKS, THREADS>>>(x, shift, out);
}

// round 4
// speedup vs baseline: 1.0242x; 1.0242x over previous
#include <cuda_runtime.h>

// RandomShiftsAug: out[n,c,j,i] = x[n, c, src_h(n,j), src_w(n,i)]
//   kx = shift[n,0], ky = shift[n,1]  (both in [0, 8])
//   th    = max(ky + j - 4, 0); src_h = th - 84*(th >= 84)
//   src_w = clamp(kx + i - 4, 0, 419)
//
// HBM-bound gather at ~7.1 TB/s logical. This round: evict-first streaming
// stores (st.global.cs) so the write stream doesn't displace the read
// overlaps L2 is already serving, plus a register diet (rows in 2 batches
// of 2, no pointer array) to restore occupancy toward 75%.

#define N_BATCH 128
#define CH      9
#define H       84
#define W       420
#define W4      (W / 4)               // 105
#define JG      (H / 4)               // 21
#define NWORK   (N_BATCH * CH * JG * W4)
#define THREADS 256
#define BLOCKS  ((NWORK + THREADS - 1) / THREADS)

__device__ __forceinline__ float4 ldg4(const float* p) {
    return __ldg((const float4*)p);
}

__device__ __forceinline__ void stcs4(float4* p, float4 v) {
    asm volatile("st.global.cs.v4.f32 [%0], {%1, %2, %3, %4};"
                 :: "l"(p), "f"(v.x), "f"(v.y), "f"(v.z), "f"(v.w)
                 : "memory");
}

// Map output row j -> source row (edge-clamp low, tile-wrap high).
__device__ __forceinline__ int src_row(int ky, int j) {
    int th = ky + j - 4;
    th = th < 0 ? 0 : th;
    return (th >= H) ? (th - H) : th;
}

template <int O>
__device__ __forceinline__ float4 combine(float4 A, float4 B) {
    float4 v;
    if (O == 0)      { v = A; }
    else if (O == 1) { v.x = A.y; v.y = A.z; v.z = A.w; v.w = B.x; }
    else if (O == 2) { v.x = A.z; v.y = A.w; v.z = B.x; v.w = B.y; }
    else             { v.x = A.w; v.y = B.x; v.z = B.y; v.w = B.z; }
    return v;
}

template <int O>
__device__ __forceinline__ void fast_path(const float* xbase, int ky, int j0,
                                          int q, float4* outp)
{
    // Two batches of 2 rows: fewer live registers than 4-row batch,
    // still 4 independent LDG.128 in flight per batch.
#pragma unroll
    for (int b = 0; b < 2; b++) {
        const float* r0 = xbase + src_row(ky, j0 + 2 * b)     * W;
        const float* r1 = xbase + src_row(ky, j0 + 2 * b + 1) * W;
        float4 A0 = ldg4(r0 + q);
        float4 A1 = ldg4(r1 + q);
        float4 B0, B1;
        if (O != 0) { B0 = ldg4(r0 + q + 4); B1 = ldg4(r1 + q + 4); }
        stcs4(outp + (2 * b)     * W4, combine<O>(A0, B0));
        stcs4(outp + (2 * b + 1) * W4, combine<O>(A1, B1));
    }
}

__global__ __launch_bounds__(THREADS)
void rand_shift_kernel(const float* __restrict__ x,
                       const int*   __restrict__ shift,
                       float4*      __restrict__ out)
{
    const int idx = blockIdx.x * THREADS + threadIdx.x;
    if (idx >= NWORK) return;

    // idx = ((nc*21 + jg)*105 + i4)
    const int i4 = idx % W4;
    const int r  = idx / W4;
    const int jg = r % JG;
    const int nc = r / JG;            // n*9 + c
    const int n  = nc / CH;

    const int kx = __ldg(&shift[2 * n]);
    const int ky = __ldg(&shift[2 * n + 1]);

    const int j0 = 4 * jg;
    const float* xbase = x + nc * H * W;
    float4* outp = out + (nc * H + j0) * W4 + i4;

    const int base = 4 * i4 + kx - 4;     // first source column
    const int o    = kx & 3;              // alignment offset (batch-uniform)
    const int a0   = base - o;            // aligned start (multiple of 4)

    bool fast;
    if (o == 0) fast = (base >= 0) && (base + 3 < W);
    else        fast = (a0 >= 0) && (a0 + 7 < W);

    if (fast) {
        if (o == 0)      fast_path<0>(xbase, ky, j0, a0, outp);
        else if (o == 1) fast_path<1>(xbase, ky, j0, a0, outp);
        else if (o == 2) fast_path<2>(xbase, ky, j0, a0, outp);
        else             fast_path<3>(xbase, ky, j0, a0, outp);
    } else {
        // Edge vectors (~2% of threads): clamped scalar gather.
        const int w0 = min(max(base,     0), W - 1);
        const int w1 = min(max(base + 1, 0), W - 1);
        const int w2 = min(max(base + 2, 0), W - 1);
        const int w3 = min(max(base + 3, 0), W - 1);
#pragma unroll
        for (int jj = 0; jj < 4; jj++) {
            const float* rp = xbase + src_row(ky, j0 + jj) * W;
            float4 v;
            v.x = __ldg(rp + w0);
            v.y = __ldg(rp + w1);
            v.z = __ldg(rp + w2);
            v.w = __ldg(rp + w3);
            stcs4(outp + jj * W4, v);
        }
    }
}

extern "C" void kernel_launch(void* const* d_in, const int* in_sizes, int n_in,
                              void* d_out, int out_size)
{
    const float* x     = (const float*)d_in[0];
    const int*   shift = (const int*)d_in[1];
    float4*      out   = (float4*)d_out;

    rand_shift_kernel<<<BLOCKS, THREADS>>>(x, shift, out);
}

// round 5
// speedup vs baseline: 1.0373x; 1.0129x over previous
#include <cuda_runtime.h>

// RandomShiftsAug: out[n,c,j,i] = x[n, c, src_h(n,j), src_w(n,i)]
//   kx = shift[n,0], ky = shift[n,1]  (both in [0, 8])
//   th    = max(ky + j - 4, 0); src_h = th - 84*(th >= 84)
//   src_w = clamp(kx + i - 4, 0, 419)
//
// At the HBM wall (~7.1 TB/s logical of ~7.3 achievable). This round:
// 6 output rows per thread (84 = 6*14, exact grid, no bounds check),
// evict-first on BOTH streams (__ldcs / st.global.cs) since every byte is
// touched once, loads in 2-row batches to cap register pressure.

#define N_BATCH 128
#define CH      9
#define H       84
#define W       420
#define W4      (W / 4)               // 105
#define RPT     6                     // rows per thread
#define JG      (H / RPT)             // 14
#define NWORK   (N_BATCH * CH * JG * W4)   // 1,693,440 = 256 * 6615
#define THREADS 256
#define BLOCKS  (NWORK / THREADS)          // 6615 exactly

__device__ __forceinline__ float4 ldcs4(const float* p) {
    float4 v;
    asm volatile("ld.global.cs.nc.v4.f32 {%0, %1, %2, %3}, [%4];"
                 : "=f"(v.x), "=f"(v.y), "=f"(v.z), "=f"(v.w)
                 : "l"(p));
    return v;
}

__device__ __forceinline__ void stcs4(float4* p, float4 v) {
    asm volatile("st.global.cs.v4.f32 [%0], {%1, %2, %3, %4};"
                 :: "l"(p), "f"(v.x), "f"(v.y), "f"(v.z), "f"(v.w)
                 : "memory");
}

// Map output row j -> source row (edge-clamp low, tile-wrap high).
__device__ __forceinline__ int src_row(int ky, int j) {
    int th = ky + j - 4;
    th = th < 0 ? 0 : th;
    return (th >= H) ? (th - H) : th;
}

template <int O>
__device__ __forceinline__ float4 combine(float4 A, float4 B) {
    float4 v;
    if (O == 0)      { v = A; }
    else if (O == 1) { v.x = A.y; v.y = A.z; v.z = A.w; v.w = B.x; }
    else if (O == 2) { v.x = A.z; v.y = A.w; v.z = B.x; v.w = B.y; }
    else             { v.x = A.w; v.y = B.x; v.z = B.y; v.w = B.z; }
    return v;
}

template <int O>
__device__ __forceinline__ void fast_path(const float* xbase, int ky, int j0,
                                          int q, float4* outp)
{
#pragma unroll
    for (int b = 0; b < RPT / 2; b++) {
        const float* r0 = xbase + src_row(ky, j0 + 2 * b)     * W;
        const float* r1 = xbase + src_row(ky, j0 + 2 * b + 1) * W;
        float4 A0 = ldcs4(r0 + q);
        float4 A1 = ldcs4(r1 + q);
        float4 B0, B1;
        if (O != 0) { B0 = ldcs4(r0 + q + 4); B1 = ldcs4(r1 + q + 4); }
        stcs4(outp + (2 * b)     * W4, combine<O>(A0, B0));
        stcs4(outp + (2 * b + 1) * W4, combine<O>(A1, B1));
    }
}

__global__ __launch_bounds__(THREADS)
void rand_shift_kernel(const float* __restrict__ x,
                       const int*   __restrict__ shift,
                       float4*      __restrict__ out)
{
    const int idx = blockIdx.x * THREADS + threadIdx.x;   // < NWORK, exact grid

    // idx = ((nc*14 + jg)*105 + i4)
    const int i4 = idx % W4;
    const int r  = idx / W4;
    const int jg = r % JG;
    const int nc = r / JG;            // n*9 + c
    const int n  = nc / CH;

    const int kx = __ldg(&shift[2 * n]);
    const int ky = __ldg(&shift[2 * n + 1]);

    const int j0 = RPT * jg;
    const float* xbase = x + nc * H * W;
    float4* outp = out + (nc * H + j0) * W4 + i4;

    const int base = 4 * i4 + kx - 4;     // first source column
    const int o    = kx & 3;              // alignment offset (batch-uniform)
    const int a0   = base - o;            // aligned start (multiple of 4)

    bool fast;
    if (o == 0) fast = (base >= 0) && (base + 3 < W);
    else        fast = (a0 >= 0) && (a0 + 7 < W);

    if (fast) {
        if (o == 0)      fast_path<0>(xbase, ky, j0, a0, outp);
        else if (o == 1) fast_path<1>(xbase, ky, j0, a0, outp);
        else if (o == 2) fast_path<2>(xbase, ky, j0, a0, outp);
        else             fast_path<3>(xbase, ky, j0, a0, outp);
    } else {
        // Edge vectors (~2% of threads): clamped scalar gather.
        const int w0 = min(max(base,     0), W - 1);
        const int w1 = min(max(base + 1, 0), W - 1);
        const int w2 = min(max(base + 2, 0), W - 1);
        const int w3 = min(max(base + 3, 0), W - 1);
#pragma unroll
        for (int jj = 0; jj < RPT; jj++) {
            const float* rp = xbase + src_row(ky, j0 + jj) * W;
            float4 v;
            v.x = __ldg(rp + w0);
            v.y = __ldg(rp + w1);
            v.z = __ldg(rp + w2);
            v.w = __ldg(rp + w3);
            stcs4(outp + jj * W4, v);
        }
    }
}

extern "C" void kernel_launch(void* const* d_in, const int* in_sizes, int n_in,
                              void* d_out, int out_size)
{
    const float* x     = (const float*)d_in[0];
    const int*   shift = (const int*)d_in[1];
    float4*      out   = (float4*)d_out;

    rand_shift_kernel<<<BLOCKS, THREADS>>>(x, shift, out);
}